// round 4
// baseline (speedup 1.0000x reference)
#include <cuda_runtime.h>
#include <cuda_bf16.h>

#define NQ 8
#define NOFF 28
// Upper-triangle flat index for 8x8 (compile-time i<=j).
#define MU(i, j) Mu[(i) * NQ + (j) - ((i) * ((i) + 1)) / 2]
// Pair index for i<j among the 28 (i<j) pairs, row-major.
#define PIDX(i, j) (7 * (i) - ((i) * ((i) - 1)) / 2 + ((j) - (i) - 1))

__global__ void __launch_bounds__(128, 6) acrobot_dyn_kernel(
    const float* __restrict__ q_in, const float* __restrict__ v_in,
    const float* __restrict__ u_in, const float* __restrict__ p,
    float* __restrict__ out, int B)
{
    // ---- uniform param-derived coefficients (once per CTA) ----
    __shared__ float sA[NOFF];  // ls_i*ls_j*(ms_suf_j - 0.5*ms_j) for i<j
    __shared__ float sD[NQ];    // diagonal of M (thread-uniform!)
    __shared__ float sIs[NQ];   // Is suffix sums (off-diag additive term)
    __shared__ float sGc[NQ];   // g * ls_j * (ms_suf_j - 0.5*ms_j)
    __shared__ float sTau[NQ];
    // per-thread parking lot for the off-diagonal triangle (lane-major, conflict-free)
    __shared__ float sMu[NOFF][128];

    if (threadIdx.x == 0) {
        float ms[NQ], ls[NQ], ms_suf[NQ], Is_suf[NQ];
#pragma unroll
        for (int i = 0; i < NQ; i++) {
            ms[i] = p[i];
            ls[i] = p[NQ + i];
            sTau[i] = p[2 * NQ + 1 + i];
        }
        const float g = p[2 * NQ];
        float a = 0.0f, c = 0.0f;
#pragma unroll
        for (int i = NQ - 1; i >= 0; i--) {
            a += ms[i];
            c += ms[i] * ls[i] * ls[i] * (1.0f / 12.0f);
            ms_suf[i] = a;
            Is_suf[i] = c;
        }
#pragma unroll
        for (int i = 0; i < NQ; i++) {
            sD[i]  = ls[i] * ls[i] * (ms_suf[i] - 0.75f * ms[i]) + Is_suf[i];
            sIs[i] = Is_suf[i];
            sGc[i] = g * ls[i] * (ms_suf[i] - 0.5f * ms[i]);
#pragma unroll
            for (int j = i + 1; j < NQ; j++)
                sA[PIDX(i, j)] = ls[i] * ls[j] * (ms_suf[j] - 0.5f * ms[j]);
        }
    }
    __syncthreads();

    const int b = blockIdx.x * blockDim.x + threadIdx.x;
    if (b >= B) return;
    const int lane = threadIdx.x;

    // ---- per-sample q, v (coalesced float4) ----
    const float4 qa = *(const float4*)(q_in + (size_t)b * NQ);
    const float4 qb = *(const float4*)(q_in + (size_t)b * NQ + 4);
    const float4 va = *(const float4*)(v_in + (size_t)b * NQ);
    const float4 vb = *(const float4*)(v_in + (size_t)b * NQ + 4);
    const float qq[NQ] = {qa.x, qa.y, qa.z, qa.w, qb.x, qb.y, qb.z, qb.w};
    const float vv[NQ] = {va.x, va.y, va.z, va.w, vb.x, vb.y, vb.z, vb.w};

    // cumsums + fast sincos
    float cv[NQ], sn[NQ], cn[NQ], vcv[NQ];
    {
        float aq = 0.0f, av = 0.0f;
#pragma unroll
        for (int i = 0; i < NQ; i++) {
            aq += qq[i];
            av += vv[i];
            cv[i] = av;
            __sincosf(aq, &sn[i], &cn[i]);
            vcv[i] = vv[i] * av;
        }
    }

    // ---- Phase B: build off-diag M into shared; Coriolis contractions in regs ----
    float r1[NQ], r2[NQ];
#pragma unroll
    for (int i = 0; i < NQ; i++) { r1[i] = 0.0f; r2[i] = 0.0f; }

#pragma unroll
    for (int i = 0; i < NQ; i++) {
#pragma unroll
        for (int j = i + 1; j < NQ; j++) {
            const float A  = sA[PIDX(i, j)];
            const float cd = cn[i] * cn[j] + sn[i] * sn[j];  // cos(cs_i - cs_j)
            const float sd = sn[i] * cn[j] - cn[i] * sn[j];  // sin(cs_i - cs_j)
            sMu[PIDX(i, j)][lane] = A * cd + sIs[j];          // park it
            const float T = A * sd;  // T[i][j]; T[j][i] = -T
            r1[i] += T * vv[j];
            r1[j] -= T * vv[i];
            r2[i] += T * vcv[j];
            r2[j] -= T * vcv[i];
        }
    }

    // ---- Phase C: rhs = taus*u - Cv - G (u loaded late) ----
    const float4 ua = *(const float4*)(u_in + (size_t)b * NQ);
    const float4 ub = *(const float4*)(u_in + (size_t)b * NQ + 4);
    const float uu[NQ] = {ua.x, ua.y, ua.z, ua.w, ub.x, ub.y, ub.z, ub.w};

    float x[NQ];
    {
        float suffR = 0.0f, suffG = 0.0f;
#pragma unroll
        for (int k = NQ - 1; k >= 0; k--) {
            suffR += vv[k] * r1[k];
            suffG += sGc[k] * sn[k];
            const float Cv = -cv[k] * r1[k] + r2[k] + suffR;
            x[k] = sTau[k] * uu[k] - Cv - suffG;
        }
    }

    // ---- Phase D: trig arrays now dead; pull triangle back, solve in registers ----
    float Mu[(NQ * (NQ + 1)) / 2];
#pragma unroll
    for (int i = 0; i < NQ; i++) {
        MU(i, i) = sD[i];
#pragma unroll
        for (int j = i + 1; j < NQ; j++)
            MU(i, j) = sMu[PIDX(i, j)][lane];
    }

    float invd[NQ];
#pragma unroll
    for (int k = 0; k < NQ; k++) {
        const float inv = __fdividef(1.0f, MU(k, k));
        invd[k] = inv;
#pragma unroll
        for (int i = k + 1; i < NQ; i++) {
            const float f = MU(k, i) * inv;  // == M[i][k]/M[k][k] (symmetry)
#pragma unroll
            for (int j = i; j < NQ; j++) MU(i, j) -= f * MU(k, j);
            x[i] -= f * x[k];
        }
    }
#pragma unroll
    for (int k = NQ - 1; k >= 0; k--) {
        float s = x[k];
#pragma unroll
        for (int j = k + 1; j < NQ; j++) s -= MU(k, j) * x[j];
        x[k] = s * invd[k];
    }

    // ---- store ----
    *(float4*)(out + (size_t)b * NQ)     = make_float4(x[0], x[1], x[2], x[3]);
    *(float4*)(out + (size_t)b * NQ + 4) = make_float4(x[4], x[5], x[6], x[7]);
}

extern "C" void kernel_launch(void* const* d_in, const int* in_sizes, int n_in,
                              void* d_out, int out_size) {
    const float* q = (const float*)d_in[0];
    const float* v = (const float*)d_in[1];
    const float* u = (const float*)d_in[2];
    const float* p = (const float*)d_in[3];
    float* out = (float*)d_out;
    const int B = in_sizes[0] / NQ;
    const int threads = 128;
    const int blocks = (B + threads - 1) / threads;
    acrobot_dyn_kernel<<<blocks, threads>>>(q, v, u, p, out, B);
}

// round 5
// speedup vs baseline: 1.0610x; 1.0610x over previous
#include <cuda_runtime.h>
#include <cuda_bf16.h>

#define NQ 8
#define NOFF 28
// Upper-triangle flat index for 8x8 (compile-time i<=j).
#define MU(i, j) Mu[(i) * NQ + (j) - ((i) * ((i) + 1)) / 2]
// Pair index for i<j among the 28 (i<j) pairs, row-major.
#define PIDX(i, j) (7 * (i) - ((i) * ((i) - 1)) / 2 + ((j) - (i) - 1))

__global__ void __launch_bounds__(128, 5) acrobot_dyn_kernel(
    const float* __restrict__ q_in, const float* __restrict__ v_in,
    const float* __restrict__ u_in, const float* __restrict__ p,
    float* __restrict__ out, int B)
{
    // ---- uniform param-derived coefficients (once per CTA) ----
    __shared__ float sA[NOFF];  // ls_i*ls_j*(ms_suf_j - 0.5*ms_j) for i<j
    __shared__ float sD[NQ];    // diagonal of M (thread-uniform)
    __shared__ float sIs[NQ];   // Is suffix sums (off-diag additive term)
    __shared__ float sGc[NQ];   // g * ls_j * (ms_suf_j - 0.5*ms_j)
    __shared__ float sTau[NQ];
    // per-thread parking lot for the off-diagonal triangle (lane-major, conflict-free)
    __shared__ float sMu[NOFF][128];

    if (threadIdx.x == 0) {
        float ms[NQ], ls[NQ], ms_suf[NQ], Is_suf[NQ];
#pragma unroll
        for (int i = 0; i < NQ; i++) {
            ms[i] = p[i];
            ls[i] = p[NQ + i];
            sTau[i] = p[2 * NQ + 1 + i];
        }
        const float g = p[2 * NQ];
        float a = 0.0f, c = 0.0f;
#pragma unroll
        for (int i = NQ - 1; i >= 0; i--) {
            a += ms[i];
            c += ms[i] * ls[i] * ls[i] * (1.0f / 12.0f);
            ms_suf[i] = a;
            Is_suf[i] = c;
        }
#pragma unroll
        for (int i = 0; i < NQ; i++) {
            sD[i]  = ls[i] * ls[i] * (ms_suf[i] - 0.75f * ms[i]) + Is_suf[i];
            sIs[i] = Is_suf[i];
            sGc[i] = g * ls[i] * (ms_suf[i] - 0.5f * ms[i]);
#pragma unroll
            for (int j = i + 1; j < NQ; j++)
                sA[PIDX(i, j)] = ls[i] * ls[j] * (ms_suf[j] - 0.5f * ms[j]);
        }
    }
    __syncthreads();

    const int b = blockIdx.x * blockDim.x + threadIdx.x;
    if (b >= B) return;
    const int lane = threadIdx.x;

    // ---- per-sample q, v (coalesced float4) ----
    const float4 qa = *(const float4*)(q_in + (size_t)b * NQ);
    const float4 qb = *(const float4*)(q_in + (size_t)b * NQ + 4);
    const float4 va = *(const float4*)(v_in + (size_t)b * NQ);
    const float4 vb = *(const float4*)(v_in + (size_t)b * NQ + 4);
    const float qq[NQ] = {qa.x, qa.y, qa.z, qa.w, qb.x, qb.y, qb.z, qb.w};
    const float vv[NQ] = {va.x, va.y, va.z, va.w, vb.x, vb.y, vb.z, vb.w};

    // cumsums + fast trig -- NO address-taking (pure scalar intrinsics)
    float cv[NQ], sn[NQ], cn[NQ];
    {
        float aq = 0.0f, av = 0.0f;
#pragma unroll
        for (int i = 0; i < NQ; i++) {
            aq += qq[i];
            av += vv[i];
            cv[i] = av;
            sn[i] = __sinf(aq);
            cn[i] = __cosf(aq);
        }
    }

    // ---- Phase B: build off-diag M into shared; Coriolis contractions in regs ----
    float r1[NQ], r2[NQ];
#pragma unroll
    for (int i = 0; i < NQ; i++) { r1[i] = 0.0f; r2[i] = 0.0f; }

#pragma unroll
    for (int i = 0; i < NQ; i++) {
#pragma unroll
        for (int j = i + 1; j < NQ; j++) {
            const float A  = sA[PIDX(i, j)];
            const float cd = cn[i] * cn[j] + sn[i] * sn[j];  // cos(cs_i - cs_j)
            const float sd = sn[i] * cn[j] - cn[i] * sn[j];  // sin(cs_i - cs_j)
            sMu[PIDX(i, j)][lane] = A * cd + sIs[j];          // park it
            const float T = A * sd;  // T[i][j]; T[j][i] = -T
            r1[i] += T * vv[j];
            r1[j] -= T * vv[i];
            r2[i] += T * vv[j] * cv[j];
            r2[j] -= T * vv[i] * cv[i];
        }
    }

    // ---- Phase C: rhs = taus*u - Cv - G (u loaded late) ----
    const float4 ua = *(const float4*)(u_in + (size_t)b * NQ);
    const float4 ub = *(const float4*)(u_in + (size_t)b * NQ + 4);
    const float uu[NQ] = {ua.x, ua.y, ua.z, ua.w, ub.x, ub.y, ub.z, ub.w};

    float x[NQ];
    {
        float suffR = 0.0f, suffG = 0.0f;
#pragma unroll
        for (int k = NQ - 1; k >= 0; k--) {
            suffR += vv[k] * r1[k];
            suffG += sGc[k] * sn[k];
            const float Cv = -cv[k] * r1[k] + r2[k] + suffR;
            x[k] = sTau[k] * uu[k] - Cv - suffG;
        }
    }

    // ---- Phase D: trig dead; pull triangle back, solve fully in registers ----
    float Mu[(NQ * (NQ + 1)) / 2];
#pragma unroll
    for (int i = 0; i < NQ; i++) {
        MU(i, i) = sD[i];
#pragma unroll
        for (int j = i + 1; j < NQ; j++)
            MU(i, j) = sMu[PIDX(i, j)][lane];
    }

    float invd[NQ];
#pragma unroll
    for (int k = 0; k < NQ; k++) {
        const float inv = __fdividef(1.0f, MU(k, k));
        invd[k] = inv;
#pragma unroll
        for (int i = k + 1; i < NQ; i++) {
            const float f = MU(k, i) * inv;  // == M[i][k]/M[k][k] (symmetry)
#pragma unroll
            for (int j = i; j < NQ; j++) MU(i, j) -= f * MU(k, j);
            x[i] -= f * x[k];
        }
    }
#pragma unroll
    for (int k = NQ - 1; k >= 0; k--) {
        float s = x[k];
#pragma unroll
        for (int j = k + 1; j < NQ; j++) s -= MU(k, j) * x[j];
        x[k] = s * invd[k];
    }

    // ---- store ----
    *(float4*)(out + (size_t)b * NQ)     = make_float4(x[0], x[1], x[2], x[3]);
    *(float4*)(out + (size_t)b * NQ + 4) = make_float4(x[4], x[5], x[6], x[7]);
}

extern "C" void kernel_launch(void* const* d_in, const int* in_sizes, int n_in,
                              void* d_out, int out_size) {
    const float* q = (const float*)d_in[0];
    const float* v = (const float*)d_in[1];
    const float* u = (const float*)d_in[2];
    const float* p = (const float*)d_in[3];
    float* out = (float*)d_out;
    const int B = in_sizes[0] / NQ;
    const int threads = 128;
    const int blocks = (B + threads - 1) / threads;
    acrobot_dyn_kernel<<<blocks, threads>>>(q, v, u, p, out, B);
}

// round 6
// speedup vs baseline: 1.1416x; 1.0759x over previous
#include <cuda_runtime.h>
#include <cuda_bf16.h>

#define NQ 8
#define NOFF 28
// Upper-triangle flat index for 8x8 (compile-time i<=j).
#define MU(i, j) Mu[(i) * NQ + (j) - ((i) * ((i) + 1)) / 2]
// Pair index for i<j among the 28 (i<j) pairs, row-major.
#define PIDX(i, j) (7 * (i) - ((i) * ((i) - 1)) / 2 + ((j) - (i) - 1))

__global__ void __launch_bounds__(128, 5) acrobot_dyn_kernel(
    const float* __restrict__ q_in, const float* __restrict__ v_in,
    const float* __restrict__ u_in, const float* __restrict__ p,
    float* __restrict__ out, int B)
{
    // ---- uniform param-derived coefficients (once per CTA) ----
    __shared__ float sA[NOFF];  // ls_i*ls_j*(ms_suf_j - 0.5*ms_j) for i<j
    __shared__ float sD[NQ];    // diagonal of M (thread-uniform)
    __shared__ float sIs[NQ];   // Is suffix sums (off-diag additive term)
    __shared__ float sGc[NQ];   // g * ls_j * (ms_suf_j - 0.5*ms_j)
    __shared__ float sTau[NQ];

    if (threadIdx.x == 0) {
        float ms[NQ], ls[NQ], ms_suf[NQ], Is_suf[NQ];
#pragma unroll
        for (int i = 0; i < NQ; i++) {
            ms[i] = p[i];
            ls[i] = p[NQ + i];
            sTau[i] = p[2 * NQ + 1 + i];
        }
        const float g = p[2 * NQ];
        float a = 0.0f, c = 0.0f;
#pragma unroll
        for (int i = NQ - 1; i >= 0; i--) {
            a += ms[i];
            c += ms[i] * ls[i] * ls[i] * (1.0f / 12.0f);
            ms_suf[i] = a;
            Is_suf[i] = c;
        }
#pragma unroll
        for (int i = 0; i < NQ; i++) {
            sD[i]  = ls[i] * ls[i] * (ms_suf[i] - 0.75f * ms[i]) + Is_suf[i];
            sIs[i] = Is_suf[i];
            sGc[i] = g * ls[i] * (ms_suf[i] - 0.5f * ms[i]);
#pragma unroll
            for (int j = i + 1; j < NQ; j++)
                sA[PIDX(i, j)] = ls[i] * ls[j] * (ms_suf[j] - 0.5f * ms[j]);
        }
    }
    __syncthreads();

    const int b = blockIdx.x * blockDim.x + threadIdx.x;
    if (b >= B) return;

    // ---- per-sample q, v (coalesced float4) ----
    const float4 qa = *(const float4*)(q_in + (size_t)b * NQ);
    const float4 qb = *(const float4*)(q_in + (size_t)b * NQ + 4);
    const float4 va = *(const float4*)(v_in + (size_t)b * NQ);
    const float4 vb = *(const float4*)(v_in + (size_t)b * NQ + 4);

    // cumsums only — NO stored trig tables (keep liveness down)
    float cs[NQ], cv[NQ], vv[NQ];
    {
        float aq = 0.0f, av = 0.0f;
        const float qq[NQ] = {qa.x, qa.y, qa.z, qa.w, qb.x, qb.y, qb.z, qb.w};
        const float tv[NQ] = {va.x, va.y, va.z, va.w, vb.x, vb.y, vb.z, vb.w};
#pragma unroll
        for (int i = 0; i < NQ; i++) {
            aq += qq[i];
            av += tv[i];
            cs[i] = aq;
            cv[i] = av;
            vv[i] = tv[i];
        }
    }

    // ---- Phase B: build M triangle in regs + Coriolis contractions ----
    // Pair trig computed on demand: cos/sin of the angle DIFFERENCE.
    float Mu[(NQ * (NQ + 1)) / 2];
    float r1[NQ], r2[NQ];
#pragma unroll
    for (int i = 0; i < NQ; i++) { r1[i] = 0.0f; r2[i] = 0.0f; }

#pragma unroll
    for (int i = 0; i < NQ; i++) {
        MU(i, i) = sD[i];
#pragma unroll
        for (int j = i + 1; j < NQ; j++) {
            const float A  = sA[PIDX(i, j)];
            const float d  = cs[i] - cs[j];
            const float cd = __cosf(d);
            const float sd = __sinf(d);
            MU(i, j) = A * cd + sIs[j];
            const float T = A * sd;  // T[i][j]; T[j][i] = -T
            r1[i] += T * vv[j];
            r1[j] -= T * vv[i];
            r2[i] += T * vv[j] * cv[j];
            r2[j] -= T * vv[i] * cv[i];
        }
    }

    // ---- Phase C: rhs = taus*u - Cv - G (u loaded late; sin recomputed) ----
    const float4 ua = *(const float4*)(u_in + (size_t)b * NQ);
    const float4 ub = *(const float4*)(u_in + (size_t)b * NQ + 4);

    float x[NQ];
    {
        const float uu[NQ] = {ua.x, ua.y, ua.z, ua.w, ub.x, ub.y, ub.z, ub.w};
        float suffR = 0.0f, suffG = 0.0f;
#pragma unroll
        for (int k = NQ - 1; k >= 0; k--) {
            suffR += vv[k] * r1[k];
            suffG += sGc[k] * __sinf(cs[k]);
            const float Cv = -cv[k] * r1[k] + r2[k] + suffR;
            x[k] = sTau[k] * uu[k] - Cv - suffG;
        }
    }

    // ---- Phase D: solve M x = rhs; symmetric GE fully in registers ----
    float invd[NQ];
#pragma unroll
    for (int k = 0; k < NQ; k++) {
        const float inv = __fdividef(1.0f, MU(k, k));
        invd[k] = inv;
#pragma unroll
        for (int i = k + 1; i < NQ; i++) {
            const float f = MU(k, i) * inv;  // == M[i][k]/M[k][k] (symmetry)
#pragma unroll
            for (int j = i; j < NQ; j++) MU(i, j) -= f * MU(k, j);
            x[i] -= f * x[k];
        }
    }
#pragma unroll
    for (int k = NQ - 1; k >= 0; k--) {
        float s = x[k];
#pragma unroll
        for (int j = k + 1; j < NQ; j++) s -= MU(k, j) * x[j];
        x[k] = s * invd[k];
    }

    // ---- store ----
    *(float4*)(out + (size_t)b * NQ)     = make_float4(x[0], x[1], x[2], x[3]);
    *(float4*)(out + (size_t)b * NQ + 4) = make_float4(x[4], x[5], x[6], x[7]);
}

extern "C" void kernel_launch(void* const* d_in, const int* in_sizes, int n_in,
                              void* d_out, int out_size) {
    const float* q = (const float*)d_in[0];
    const float* v = (const float*)d_in[1];
    const float* u = (const float*)d_in[2];
    const float* p = (const float*)d_in[3];
    float* out = (float*)d_out;
    const int B = in_sizes[0] / NQ;
    const int threads = 128;
    const int blocks = (B + threads - 1) / threads;
    acrobot_dyn_kernel<<<blocks, threads>>>(q, v, u, p, out, B);
}

// round 7
// speedup vs baseline: 1.1549x; 1.0117x over previous
#include <cuda_runtime.h>
#include <cuda_bf16.h>

#define NQ 8
#define FULLMASK 0xffffffffu

// One sample per 8 lanes. Lane r owns matrix row r.
__global__ void __launch_bounds__(256) acrobot_dyn_kernel(
    const float* __restrict__ q_in, const float* __restrict__ v_in,
    const float* __restrict__ u_in, const float* __restrict__ p,
    float* __restrict__ out, int Btot /* = B*NQ */)
{
    // ---- uniform coefficient matrices (once per CTA), padded to 9 cols ----
    __shared__ float sAm[NQ][9];   // A[i][j] = ls_i*ls_j*(ms_suf_max - 0.5*ms_max); 0 on diag
    __shared__ float sIsM[NQ][9];  // Is_suf[max(i,j)] off-diag; FULL diagonal D[i] on diag
    __shared__ float sGc[NQ];      // g * ls_k * (ms_suf_k - 0.5*ms_k)
    __shared__ float sTau[NQ];

    if (threadIdx.x == 0) {
        float ms[NQ], ls[NQ], ms_suf[NQ], Is_suf[NQ];
#pragma unroll
        for (int i = 0; i < NQ; i++) {
            ms[i] = p[i];
            ls[i] = p[NQ + i];
            sTau[i] = p[2 * NQ + 1 + i];
        }
        const float g = p[2 * NQ];
        float a = 0.0f, c = 0.0f;
#pragma unroll
        for (int i = NQ - 1; i >= 0; i--) {
            a += ms[i];
            c += ms[i] * ls[i] * ls[i] * (1.0f / 12.0f);
            ms_suf[i] = a;
            Is_suf[i] = c;
        }
#pragma unroll
        for (int i = 0; i < NQ; i++) {
            sGc[i] = g * ls[i] * (ms_suf[i] - 0.5f * ms[i]);
#pragma unroll
            for (int j = 0; j < NQ; j++) {
                const int mx = (i > j) ? i : j;
                if (i == j) {
                    sAm[i][j]  = 0.0f;  // kills off-diag formula on diagonal
                    sIsM[i][j] = ls[i] * ls[i] * (ms_suf[i] - 0.75f * ms[i]) + Is_suf[i];
                } else {
                    sAm[i][j]  = ls[i] * ls[j] * (ms_suf[mx] - 0.5f * ms[mx]);
                    sIsM[i][j] = Is_suf[mx];
                }
            }
        }
    }
    __syncthreads();

    const int gid = blockIdx.x * blockDim.x + threadIdx.x;  // element index
    const int r = threadIdx.x & 7;                           // row within sample
    const bool valid = (gid < Btot);
    const int g_safe = valid ? gid : (Btot - 1);             // keep shuffles uniform

    // ---- per-element loads (fully coalesced 32b) ----
    const float qr = q_in[g_safe];
    const float vr = v_in[g_safe];

    // segmented inclusive scans (width 8): cs = cumsum(q), cv = cumsum(v)
    float cs = qr, cv = vr;
#pragma unroll
    for (int d = 1; d < NQ; d <<= 1) {
        const float tq = __shfl_up_sync(FULLMASK, cs, d, NQ);
        const float tv = __shfl_up_sync(FULLMASK, cv, d, NQ);
        if (r >= d) { cs += tq; cv += tv; }
    }

    const float sn = __sinf(cs);
    const float cn = __cosf(cs);
    const float vcv = vr * cv;

    // ---- build own matrix row + Coriolis contractions ----
    float m[NQ];
    float r1 = 0.0f, r2 = 0.0f;
#pragma unroll
    for (int j = 0; j < NQ; j++) {
        const float snj  = __shfl_sync(FULLMASK, sn, j, NQ);
        const float cnj  = __shfl_sync(FULLMASK, cn, j, NQ);
        const float vj   = __shfl_sync(FULLMASK, vr, j, NQ);
        const float vcvj = __shfl_sync(FULLMASK, vcv, j, NQ);
        const float A  = sAm[r][j];
        const float cd = cn * cnj + sn * snj;   // cos(cs_r - cs_j)
        const float sd = sn * cnj - cn * snj;   // sin(cs_r - cs_j)
        m[j] = A * cd + sIsM[r][j];             // diag: A=0, sIsM=D -> correct
        const float T = A * sd;                 // T[r][j]; zero on diag
        r1 += T * vj;
        r2 += T * vcvj;
    }

    // ---- rhs: suffix sums across lanes ----
    // suffR_k = sum_{i>=k} v_i*r1_i ; suffG_k = sum_{i>=k} Gc_i*sin(cs_i)
    float suffR = vr * r1;
    float suffG = sGc[r] * sn;
#pragma unroll
    for (int d = 1; d < NQ; d <<= 1) {
        const float tR = __shfl_down_sync(FULLMASK, suffR, d, NQ);
        const float tG = __shfl_down_sync(FULLMASK, suffG, d, NQ);
        if (r + d < NQ) { suffR += tR; suffG += tG; }
    }

    const float ur = u_in[g_safe];
    const float Cv = -cv * r1 + r2 + suffR;
    float x = sTau[r] * ur - Cv - suffG;

    // ---- lane-parallel Gaussian elimination (no pivoting; SPD) ----
    float dinv = 0.0f;  // 1/m[r][r] captured when r is pivot
#pragma unroll
    for (int k = 0; k < NQ; k++) {
        const float pivkk = __shfl_sync(FULLMASK, m[k], k, NQ);
        const float inv = __fdividef(1.0f, pivkk);
        if (r == k) dinv = inv;
        if (k < NQ - 1) {
            const float f = m[k] * inv;
            const bool act = (r > k);
#pragma unroll
            for (int j = k + 1; j < NQ; j++) {
                const float pj = __shfl_sync(FULLMASK, m[j], k, NQ);
                if (act) m[j] -= f * pj;
            }
            const float px = __shfl_sync(FULLMASK, x, k, NQ);
            if (act) x -= f * px;
        }
    }

    // ---- back substitution ----
    float sol = 0.0f;
#pragma unroll
    for (int k = NQ - 1; k >= 0; k--) {
        const float xk = __shfl_sync(FULLMASK, x, k, NQ);
        const float dk = __shfl_sync(FULLMASK, dinv, k, NQ);
        const float s = xk * dk;  // solved x_k
        if (r == k) sol = s;
        if (r < k) x -= m[k] * s;
    }

    if (valid) out[gid] = sol;
}

extern "C" void kernel_launch(void* const* d_in, const int* in_sizes, int n_in,
                              void* d_out, int out_size) {
    const float* q = (const float*)d_in[0];
    const float* v = (const float*)d_in[1];
    const float* u = (const float*)d_in[2];
    const float* p = (const float*)d_in[3];
    float* out = (float*)d_out;
    const int Btot = in_sizes[0];  // B*NQ elements
    const int threads = 256;
    const int blocks = (Btot + threads - 1) / threads;
    acrobot_dyn_kernel<<<blocks, threads>>>(q, v, u, p, out, Btot);
}

// round 8
// speedup vs baseline: 1.7124x; 1.4826x over previous
#include <cuda_runtime.h>
#include <cuda_bf16.h>

#define NQ 8
#define FULLMASK 0xffffffffu

// One sample per 4 lanes; lane l owns matrix rows e0=2l and e1=2l+1.
__global__ void __launch_bounds__(256) acrobot_dyn_kernel(
    const float* __restrict__ q_in, const float* __restrict__ v_in,
    const float* __restrict__ u_in, const float* __restrict__ p,
    float* __restrict__ out, int Btot /* = B*NQ */)
{
    // ---- uniform coefficient tables (once per CTA) ----
    // sCo[i][j] = (A, IsOrD): off-diag A = ls_i*ls_j*(ms_suf_mx - .5 ms_mx), Is_suf[mx];
    //             diag       A = 0,     D[i].
    __shared__ float2 sCo[NQ][NQ + 1];
    __shared__ float sGc[NQ];   // g * ls_k * (ms_suf_k - 0.5*ms_k)
    __shared__ float sTau[NQ];

    if (threadIdx.x == 0) {
        float ms[NQ], ls[NQ], ms_suf[NQ], Is_suf[NQ];
#pragma unroll
        for (int i = 0; i < NQ; i++) {
            ms[i] = p[i];
            ls[i] = p[NQ + i];
            sTau[i] = p[2 * NQ + 1 + i];
        }
        const float g = p[2 * NQ];
        float a = 0.0f, c = 0.0f;
#pragma unroll
        for (int i = NQ - 1; i >= 0; i--) {
            a += ms[i];
            c += ms[i] * ls[i] * ls[i] * (1.0f / 12.0f);
            ms_suf[i] = a;
            Is_suf[i] = c;
        }
#pragma unroll
        for (int i = 0; i < NQ; i++) {
            sGc[i] = g * ls[i] * (ms_suf[i] - 0.5f * ms[i]);
#pragma unroll
            for (int j = 0; j < NQ; j++) {
                if (i == j) {
                    sCo[i][j] = make_float2(
                        0.0f, ls[i] * ls[i] * (ms_suf[i] - 0.75f * ms[i]) + Is_suf[i]);
                } else {
                    const int mx = (i > j) ? i : j;
                    sCo[i][j] = make_float2(
                        ls[i] * ls[j] * (ms_suf[mx] - 0.5f * ms[mx]), Is_suf[mx]);
                }
            }
        }
    }
    __syncthreads();

    const int nPairs = Btot >> 1;                        // float2 elements
    int t2 = blockIdx.x * blockDim.x + threadIdx.x;      // pair index
    const bool valid = (t2 < nPairs);
    if (!valid) t2 = nPairs - 1;                         // keep shuffle groups uniform
    const int l = threadIdx.x & 3;                       // lane within sample
    const int e0 = 2 * l, e1 = 2 * l + 1;                // owned rows/elements

    // ---- coalesced float2 loads ----
    const float2 q2 = ((const float2*)q_in)[t2];
    const float2 v2 = ((const float2*)v_in)[t2];
    const float v0 = v2.x, v1 = v2.y;

    // ---- segmented scans over 8 elements (2/lane, width-4 shuffles) ----
    float sq = q2.x + q2.y;   // lane totals
    float sv = v0 + v1;
#pragma unroll
    for (int d = 1; d < 4; d <<= 1) {
        const float uq = __shfl_up_sync(FULLMASK, sq, d, 4);
        const float uv = __shfl_up_sync(FULLMASK, sv, d, 4);
        if (l >= d) { sq += uq; sv += uv; }
    }
    const float cs1 = sq, cs0 = sq - q2.y;   // inclusive cumsum of q
    const float cv1 = sv, cv0 = sv - v1;     // inclusive cumsum of v

    const float sn0 = __sinf(cs0), cn0 = __cosf(cs0);
    const float sn1 = __sinf(cs1), cn1 = __cosf(cs1);
    const float vcv0 = v0 * cv0, vcv1 = v1 * cv1;

    // ---- build both owned matrix rows + Coriolis contractions ----
    float m0[NQ], m1[NQ];
    float r10 = 0.0f, r20 = 0.0f, r11 = 0.0f, r21 = 0.0f;
#pragma unroll
    for (int j = 0; j < NQ; j++) {
        const int src = j >> 1;  // compile-time
        const float snj  = __shfl_sync(FULLMASK, (j & 1) ? sn1 : sn0, src, 4);
        const float cnj  = __shfl_sync(FULLMASK, (j & 1) ? cn1 : cn0, src, 4);
        const float vj   = __shfl_sync(FULLMASK, (j & 1) ? v1  : v0,  src, 4);
        const float vcvj = __shfl_sync(FULLMASK, (j & 1) ? vcv1 : vcv0, src, 4);

        const float2 c0 = sCo[e0][j];
        const float cd0 = cn0 * cnj + sn0 * snj;
        const float sd0 = sn0 * cnj - cn0 * snj;
        m0[j] = c0.x * cd0 + c0.y;
        const float T0 = c0.x * sd0;
        r10 += T0 * vj;
        r20 += T0 * vcvj;

        const float2 c1 = sCo[e1][j];
        const float cd1 = cn1 * cnj + sn1 * snj;
        const float sd1 = sn1 * cnj - cn1 * snj;
        m1[j] = c1.x * cd1 + c1.y;
        const float T1 = c1.x * sd1;
        r11 += T1 * vj;
        r21 += T1 * vcvj;
    }

    // ---- suffix sums (inclusive, from high index down) ----
    const float gA = sGc[e0] * sn0;
    const float gB = sGc[e1] * sn1;
    const float rA = v0 * r10;
    float sR = rA + v1 * r11;
    float sG = gA + gB;
#pragma unroll
    for (int d = 1; d < 4; d <<= 1) {
        const float dR = __shfl_down_sync(FULLMASK, sR, d, 4);
        const float dG = __shfl_down_sync(FULLMASK, sG, d, 4);
        if (l + d < 4) { sR += dR; sG += dG; }
    }
    const float suffR0 = sR, suffR1 = sR - rA;
    const float suffG0 = sG, suffG1 = sG - gA;

    // ---- rhs ----
    const float2 u2 = ((const float2*)u_in)[t2];
    float x0 = sTau[e0] * u2.x - (-cv0 * r10 + r20 + suffR0) - suffG0;
    float x1 = sTau[e1] * u2.y - (-cv1 * r11 + r21 + suffR1) - suffG1;

    // ---- lane-parallel Gaussian elimination (SPD, no pivoting) ----
    float dinv0 = 0.0f, dinv1 = 0.0f;
#pragma unroll
    for (int k = 0; k < NQ; k++) {
        const int ok = k >> 1;  // owner lane (compile-time)
        const float pivkk = __shfl_sync(FULLMASK, (k & 1) ? m1[k] : m0[k], ok, 4);
        const float inv = __fdividef(1.0f, pivkk);
        if (l == ok) { if (k & 1) dinv1 = inv; else dinv0 = inv; }
        const bool a0 = (e0 > k), a1 = (e1 > k);
        const float f0 = m0[k] * inv;
        const float f1 = m1[k] * inv;
#pragma unroll
        for (int j = k + 1; j < NQ; j++) {
            const float pj = __shfl_sync(FULLMASK, (k & 1) ? m1[j] : m0[j], ok, 4);
            if (a0) m0[j] -= f0 * pj;
            if (a1) m1[j] -= f1 * pj;
        }
        const float px = __shfl_sync(FULLMASK, (k & 1) ? x1 : x0, ok, 4);
        if (a0) x0 -= f0 * px;
        if (a1) x1 -= f1 * px;
    }

    // ---- back substitution ----
#pragma unroll
    for (int k = NQ - 1; k >= 0; k--) {
        const int ok = k >> 1;
        const float sOwn = (k & 1) ? x1 * dinv1 : x0 * dinv0;
        const float s = __shfl_sync(FULLMASK, sOwn, ok, 4);
        if (l == ok) { if (k & 1) x1 = s; else x0 = s; }
        if (e0 < k) x0 -= m0[k] * s;
        if (e1 < k) x1 -= m1[k] * s;
    }

    if (valid) ((float2*)out)[t2] = make_float2(x0, x1);
}

extern "C" void kernel_launch(void* const* d_in, const int* in_sizes, int n_in,
                              void* d_out, int out_size) {
    const float* q = (const float*)d_in[0];
    const float* v = (const float*)d_in[1];
    const float* u = (const float*)d_in[2];
    const float* p = (const float*)d_in[3];
    float* out = (float*)d_out;
    const int Btot = in_sizes[0];       // B*NQ elements
    const int nThreads = Btot / 2;      // one thread per float2
    const int threads = 256;
    const int blocks = (nThreads + threads - 1) / threads;
    acrobot_dyn_kernel<<<blocks, threads>>>(q, v, u, p, out, Btot);
}